// round 9
// baseline (speedup 1.0000x reference)
#include <cuda_runtime.h>
#include <cuda_fp16.h>
#include <cstdint>

// Problem constants (fixed by the dataset)
#define BB 4
#define NN 50000
#define RR 100000
#define EE 1600000
#define D1 32
#define D2 16
#define NEG 0.2f

#define MW_R ((RR + 31) / 32)
#define MW_N ((NN + 31) / 32)

#define SCAN_T (EE / 8)                    // 200000 threads, 8 edges each
#define SCAN_B ((SCAN_T + 255) / 256)      // 782 blocks per array
#define H1_W   (NN * BB)                   // 200000 h1 rows (one warp each)
#define H1_B   ((H1_W + 7) / 8)            // 25000 h1 blocks
#define H1_HALF (H1_B / 2)                 // 12500 per carrier kernel

#define CHUNK 2048
#define NB_WI ((NN + CHUNK - 1) / CHUNK)   // 25
#define NB_W  ((RR + CHUNK - 1) / CHUNK)   // 49
#define NB_TOT (NB_WI + NB_W)              // 74

// ---------------- device scratch (zero-init at load; counters/masks re-zeroed in tail)
__device__ __half g_h1[NN * BB * D1];      // 12.8 MB [n][b][32] fp16
__device__ float g_T1[RR * BB * D1];       // 51.2 MB [r][b][32]
__device__ float g_h2[NN * BB * D2];       // 12.8 MB
__device__ float g_T2[RR * BB * D2];       // 25.6 MB

__device__ int  g_cntWi[NN], g_cntW[RR];   // histograms (must be zero at call entry)
__device__ int  g_ptrWi[NN], g_ptrW[RR];   // CSR row starts
__device__ int  g_posWi[NN], g_posW[RR];   // scatter cursors (recomputed each call)
__device__ int2 g_csrWi[EE], g_csrW[EE];   // (col, val) per edge, grouped by row
__device__ int  g_bsum[NB_TOT], g_boff[NB_TOT];

__device__ unsigned g_mT1[MW_R], g_mT2[MW_R], g_mH2[MW_N];  // dedup masks
__device__ int g_listT1[RR], g_listH2[NN], g_listT2[RR];
__device__ int g_nT1, g_nH2, g_nT2;

// ---------------- h1: 8 warps/block, one (n,b) row per warp (R4 pattern) -------------
__device__ __forceinline__ void h1_block(int vb, const float* __restrict__ x,
                                         const float* __restrict__ W1) {
    __shared__ float sW[D1 * D1];
    int t = threadIdx.x;
    for (int i = t; i < D1 * D1; i += 256) sW[i] = W1[i];
    __syncthreads();
    int w = vb * 8 + (t >> 5);
    if (w >= H1_W) return;
    int lane = t & 31;
    int n = w >> 2, b = w & 3;
    float xv = __ldg(&x[((size_t)b * NN + n) * D1 + lane]);
    float a0 = 0.f, a1 = 0.f;
#pragma unroll
    for (int k = 0; k < D1; k += 2) {
        a0 = fmaf(__shfl_sync(0xffffffffu, xv, k),     sW[k * D1 + lane],       a0);
        a1 = fmaf(__shfl_sync(0xffffffffu, xv, k + 1), sW[(k + 1) * D1 + lane], a1);
    }
    g_h1[(size_t)w * D1 + lane] = __float2half(a0 + a1);
}

// ---------------- 1) histogram of both row arrays (+ first half of h1) ---------------
__global__ void __launch_bounds__(256) k_hist(const int* __restrict__ wiRows,
        const int* __restrict__ wRows,
        const float* __restrict__ x, const float* __restrict__ W1) {
    if (blockIdx.x >= 2 * SCAN_B) { h1_block(blockIdx.x - 2 * SCAN_B, x, W1); return; }
    bool isWi = blockIdx.x < SCAN_B;
    int bi = isWi ? blockIdx.x : blockIdx.x - SCAN_B;
    int t = bi * 256 + threadIdx.x;
    if (t >= SCAN_T) return;
    const int* rows = isWi ? wiRows : wRows;
    int* cnt = isWi ? g_cntWi : g_cntW;
    int base = t * 8;
    int4 a = __ldg((const int4*)(rows + base));
    int4 b = __ldg((const int4*)(rows + base + 4));
    atomicAdd(&cnt[a.x], 1); atomicAdd(&cnt[a.y], 1);
    atomicAdd(&cnt[a.z], 1); atomicAdd(&cnt[a.w], 1);
    atomicAdd(&cnt[b.x], 1); atomicAdd(&cnt[b.y], 1);
    atomicAdd(&cnt[b.z], 1); atomicAdd(&cnt[b.w], 1);
}

// ---------------- 2) chunked prefix sum: A) chunk totals --------------------------------
__global__ void __launch_bounds__(256) k_scanA() {
    int blk = blockIdx.x;
    const int* cnt; int off, len;
    if (blk < NB_WI) { cnt = g_cntWi; off = blk * CHUNK; len = NN; }
    else             { cnt = g_cntW;  off = (blk - NB_WI) * CHUNK; len = RR; }
    int s = 0;
    for (int i = threadIdx.x; i < CHUNK; i += 256) {
        int idx = off + i;
        if (idx < len) s += cnt[idx];
    }
    __shared__ int ws[8];
#pragma unroll
    for (int o = 16; o; o >>= 1) s += __shfl_xor_sync(0xffffffffu, s, o);
    if ((threadIdx.x & 31) == 0) ws[threadIdx.x >> 5] = s;
    __syncthreads();
    if (threadIdx.x == 0) {
        int tot = 0;
#pragma unroll
        for (int i = 0; i < 8; i++) tot += ws[i];
        g_bsum[blk] = tot;
    }
}

// ---------------- 2B) scan the 74 chunk totals (per-array segments) ------------------
__global__ void k_scanB() {
    if (threadIdx.x == 0) {
        int run = 0;
        for (int i = 0; i < NB_WI; i++) { g_boff[i] = run; run += g_bsum[i]; }
        run = 0;
        for (int i = NB_WI; i < NB_TOT; i++) { g_boff[i] = run; run += g_bsum[i]; }
    }
}

// ---------------- 2C) intra-chunk exclusive scan -> ptr and pos ----------------------
__global__ void __launch_bounds__(256) k_scanC() {
    int blk = blockIdx.x;
    const int* cnt; int off, len; bool isWi;
    if (blk < NB_WI) { cnt = g_cntWi; off = blk * CHUNK; len = NN; isWi = true; }
    else             { cnt = g_cntW;  off = (blk - NB_WI) * CHUNK; len = RR; isWi = false; }
    int t = threadIdx.x, lane = t & 31, warp = t >> 5;
    int idx0 = off + t * 8;
    int vals[8]; int s = 0;
#pragma unroll
    for (int j = 0; j < 8; j++) {
        int idx = idx0 + j;
        int v = (idx < len) ? cnt[idx] : 0;
        vals[j] = s; s += v;
    }
    int pre = s;
#pragma unroll
    for (int o = 1; o < 32; o <<= 1) {
        int n = __shfl_up_sync(0xffffffffu, pre, o);
        if (lane >= o) pre += n;
    }
    int warpExcl = pre - s;
    __shared__ int wtot[8];
    if (lane == 31) wtot[warp] = pre;
    __syncthreads();
    int warpOff = 0;
    for (int i = 0; i < warp; i++) warpOff += wtot[i];
    int baseOff = g_boff[blk] + warpOff + warpExcl;
#pragma unroll
    for (int j = 0; j < 8; j++) {
        int idx = idx0 + j;
        if (idx < len) {
            int p = baseOff + vals[j];
            if (isWi) { g_ptrWi[idx] = p; g_posWi[idx] = p; }
            else      { g_ptrW[idx]  = p; g_posW[idx]  = p; }
        }
    }
}

// ---------------- 3) scatter edges into CSR (+ second half of h1) --------------------
__global__ void __launch_bounds__(256) k_scat(const int* __restrict__ wiRows,
        const int* __restrict__ wiCols, const float* __restrict__ wiVals,
        const int* __restrict__ wRows, const int* __restrict__ wCols,
        const float* __restrict__ wVals,
        const float* __restrict__ x, const float* __restrict__ W1) {
    if (blockIdx.x >= 2 * SCAN_B) { h1_block(blockIdx.x - 2 * SCAN_B + H1_HALF, x, W1); return; }
    bool isWi = blockIdx.x < SCAN_B;
    int bi = isWi ? blockIdx.x : blockIdx.x - SCAN_B;
    int t = bi * 256 + threadIdx.x;
    if (t >= SCAN_T) return;
    const int* rows = isWi ? wiRows : wRows;
    const int* cols = isWi ? wiCols : wCols;
    const float* vals = isWi ? wiVals : wVals;
    int* pos = isWi ? g_posWi : g_posW;
    int2* csr = isWi ? g_csrWi : g_csrW;
    int base = t * 8;
    int4 r0 = __ldg((const int4*)(rows + base));
    int4 r1 = __ldg((const int4*)(rows + base + 4));
    int4 c0 = __ldg((const int4*)(cols + base));
    int4 c1 = __ldg((const int4*)(cols + base + 4));
    float4 v0 = __ldg((const float4*)(vals + base));
    float4 v1 = __ldg((const float4*)(vals + base + 4));
    int rr[8] = {r0.x, r0.y, r0.z, r0.w, r1.x, r1.y, r1.z, r1.w};
    int cc[8] = {c0.x, c0.y, c0.z, c0.w, c1.x, c1.y, c1.z, c1.w};
    float vv[8] = {v0.x, v0.y, v0.z, v0.w, v1.x, v1.y, v1.z, v1.w};
#pragma unroll
    for (int j = 0; j < 8; j++) {
        int slot = atomicAdd(&pos[rr[j]], 1);
        csr[slot] = make_int2(cc[j], __float_as_int(vv[j]));
    }
}

// ---------------- 4) expand: output nodes -> T2 rows ---------------------------------
__global__ void k_e1() {
    int warp = threadIdx.x >> 5, lane = threadIdx.x & 31;
    if (warp >= 2) return;
    int n = NN - 2 + warp;
    int p = g_ptrWi[n], c = g_cntWi[n];
    for (int i = lane; i < c; i += 32) {
        int col = g_csrWi[p + i].x;
        unsigned bit = 1u << (col & 31);
        unsigned old = atomicOr(&g_mT2[col >> 5], bit);
        if (!(old & bit)) g_listT2[atomicAdd(&g_nT2, 1)] = col;
    }
}

// ---------------- 5) expand: T2 rows -> h2 nodes -------------------------------------
__global__ void __launch_bounds__(256) k_e2() {
    int lane = threadIdx.x & 31;
    int gw = blockIdx.x * 8 + (threadIdx.x >> 5), nw = gridDim.x * 8;
    int nact = g_nT2;
    for (int i = gw; i < nact; i += nw) {
        int row = g_listT2[i];
        int p = g_ptrW[row], c = g_cntW[row];
        for (int k = lane; k < c; k += 32) {
            int col = g_csrW[p + k].x;
            unsigned bit = 1u << (col & 31);
            unsigned old = atomicOr(&g_mH2[col >> 5], bit);
            if (!(old & bit)) g_listH2[atomicAdd(&g_nH2, 1)] = col;
        }
    }
}

// ---------------- 6) expand: h2 nodes -> T1 rows -------------------------------------
__global__ void __launch_bounds__(256) k_e3() {
    int lane = threadIdx.x & 31;
    int gw = blockIdx.x * 8 + (threadIdx.x >> 5), nw = gridDim.x * 8;
    int nact = g_nH2;
    for (int i = gw; i < nact; i += nw) {
        int node = g_listH2[i];
        int p = g_ptrWi[node], c = g_cntWi[node];
        for (int k = lane; k < c; k += 32) {
            int col = g_csrWi[p + k].x;
            unsigned bit = 1u << (col & 31);
            unsigned old = atomicOr(&g_mT1[col >> 5], bit);
            if (!(old & bit)) g_listT1[atomicAdd(&g_nT1, 1)] = col;
        }
    }
}

// ---------------- 7) T1[row] = sum CSR(w) slice * h1 ---------------------------------
__global__ void __launch_bounds__(256) k_T1() {
    int lane = threadIdx.x & 31;
    int gw = blockIdx.x * 8 + (threadIdx.x >> 5), nw = gridDim.x * 8;
    int b = lane >> 3, q = lane & 7;
    int nact = g_nT1;
    for (int i = gw; i < nact; i += nw) {
        int row = g_listT1[i];
        int p = g_ptrW[row], c = g_cntW[row];
        const int2* bk = &g_csrW[p];
        float4 acc = make_float4(0.f, 0.f, 0.f, 0.f);
        int k = 0;
        for (; k + 4 <= c; k += 4) {
            int2 e0 = __ldg(&bk[k]),     e1 = __ldg(&bk[k + 1]);
            int2 e2 = __ldg(&bk[k + 2]), e3 = __ldg(&bk[k + 3]);
            uint2 u0 = *(const uint2*)&g_h1[((size_t)e0.x * BB + b) * D1 + q * 4];
            uint2 u1 = *(const uint2*)&g_h1[((size_t)e1.x * BB + b) * D1 + q * 4];
            uint2 u2 = *(const uint2*)&g_h1[((size_t)e2.x * BB + b) * D1 + q * 4];
            uint2 u3 = *(const uint2*)&g_h1[((size_t)e3.x * BB + b) * D1 + q * 4];
            float v0 = __int_as_float(e0.y), v1 = __int_as_float(e1.y);
            float v2 = __int_as_float(e2.y), v3 = __int_as_float(e3.y);
            float2 a01, a23;
            a01 = __half22float2(*(__half2*)&u0.x); a23 = __half22float2(*(__half2*)&u0.y);
            acc.x = fmaf(v0, a01.x, acc.x); acc.y = fmaf(v0, a01.y, acc.y);
            acc.z = fmaf(v0, a23.x, acc.z); acc.w = fmaf(v0, a23.y, acc.w);
            a01 = __half22float2(*(__half2*)&u1.x); a23 = __half22float2(*(__half2*)&u1.y);
            acc.x = fmaf(v1, a01.x, acc.x); acc.y = fmaf(v1, a01.y, acc.y);
            acc.z = fmaf(v1, a23.x, acc.z); acc.w = fmaf(v1, a23.y, acc.w);
            a01 = __half22float2(*(__half2*)&u2.x); a23 = __half22float2(*(__half2*)&u2.y);
            acc.x = fmaf(v2, a01.x, acc.x); acc.y = fmaf(v2, a01.y, acc.y);
            acc.z = fmaf(v2, a23.x, acc.z); acc.w = fmaf(v2, a23.y, acc.w);
            a01 = __half22float2(*(__half2*)&u3.x); a23 = __half22float2(*(__half2*)&u3.y);
            acc.x = fmaf(v3, a01.x, acc.x); acc.y = fmaf(v3, a01.y, acc.y);
            acc.z = fmaf(v3, a23.x, acc.z); acc.w = fmaf(v3, a23.y, acc.w);
        }
        for (; k < c; k++) {
            int2 e0 = __ldg(&bk[k]);
            float v = __int_as_float(e0.y);
            uint2 u0 = *(const uint2*)&g_h1[((size_t)e0.x * BB + b) * D1 + q * 4];
            float2 a01 = __half22float2(*(__half2*)&u0.x);
            float2 a23 = __half22float2(*(__half2*)&u0.y);
            acc.x = fmaf(v, a01.x, acc.x); acc.y = fmaf(v, a01.y, acc.y);
            acc.z = fmaf(v, a23.x, acc.z); acc.w = fmaf(v, a23.y, acc.w);
        }
        *(float4*)&g_T1[((size_t)row * BB + b) * D1 + q * 4] = acc;
    }
}

// ---------------- 8) fused x1 + h2 over active nodes (CSR(wi) slices) ----------------
__global__ void __launch_bounds__(256) k_x1h2(const float* __restrict__ diag1,
                                              const float* __restrict__ W2) {
    __shared__ float sW[D1 * D2];
    __shared__ float sX[8][BB * D1];
    int t = threadIdx.x;
    for (int i = t; i < D1 * D2; i += 256) sW[i] = W2[i];
    __syncthreads();
    int lane = t & 31, wl = t >> 5;
    int gw = blockIdx.x * 8 + wl, nw = gridDim.x * 8;
    int b = lane >> 3, q = lane & 7;
    int nact = g_nH2;
    for (int i = gw; i < nact; i += nw) {
        int node = g_listH2[i];
        int p = g_ptrWi[node], c = g_cntWi[node];
        const int2* bk = &g_csrWi[p];
        float4 acc = make_float4(0.f, 0.f, 0.f, 0.f);
        int k = 0;
        for (; k + 2 <= c; k += 2) {
            int2 e0 = __ldg(&bk[k]), e1 = __ldg(&bk[k + 1]);
            float v0 = __int_as_float(e0.y) * __ldg(&diag1[e0.x]);
            float v1 = __int_as_float(e1.y) * __ldg(&diag1[e1.x]);
            float4 t0 = *(const float4*)&g_T1[((size_t)e0.x * BB + b) * D1 + q * 4];
            float4 t1 = *(const float4*)&g_T1[((size_t)e1.x * BB + b) * D1 + q * 4];
            acc.x = fmaf(v0, t0.x, acc.x); acc.y = fmaf(v0, t0.y, acc.y);
            acc.z = fmaf(v0, t0.z, acc.z); acc.w = fmaf(v0, t0.w, acc.w);
            acc.x = fmaf(v1, t1.x, acc.x); acc.y = fmaf(v1, t1.y, acc.y);
            acc.z = fmaf(v1, t1.z, acc.z); acc.w = fmaf(v1, t1.w, acc.w);
        }
        for (; k < c; k++) {
            int2 e0 = __ldg(&bk[k]);
            float v = __int_as_float(e0.y) * __ldg(&diag1[e0.x]);
            float4 tv = *(const float4*)&g_T1[((size_t)e0.x * BB + b) * D1 + q * 4];
            acc.x = fmaf(v, tv.x, acc.x); acc.y = fmaf(v, tv.y, acc.y);
            acc.z = fmaf(v, tv.z, acc.z); acc.w = fmaf(v, tv.w, acc.w);
        }
        acc.x = acc.x > 0.f ? acc.x : NEG * acc.x;
        acc.y = acc.y > 0.f ? acc.y : NEG * acc.y;
        acc.z = acc.z > 0.f ? acc.z : NEG * acc.z;
        acc.w = acc.w > 0.f ? acc.w : NEG * acc.w;
        *(float4*)&sX[wl][b * D1 + q * 4] = acc;
        __syncwarp();
        int j = lane & 7;
        const float* xr = &sX[wl][b * D1];
        float a0 = 0.f, a1 = 0.f;
#pragma unroll
        for (int kk = 0; kk < D1; kk++) {
            float xv = xr[kk];
            a0 = fmaf(xv, sW[kk * D2 + j], a0);
            a1 = fmaf(xv, sW[kk * D2 + j + 8], a1);
        }
        g_h2[((size_t)node * BB + b) * D2 + j] = a0;
        g_h2[((size_t)node * BB + b) * D2 + j + 8] = a1;
        __syncwarp();
    }
}

// ---------------- 9) T2 over active rows (CSR(w) slices, h2 gather) ------------------
__global__ void __launch_bounds__(256) k_T2() {
    int lane = threadIdx.x & 31;
    int gw = blockIdx.x * 8 + (threadIdx.x >> 5), nw = gridDim.x * 8;
    int nact = g_nT2;
    int b = (lane >> 2) & 3, q = lane & 3;
    for (int i = gw; i < nact; i += nw) {
        int row = g_listT2[i];
        int p = g_ptrW[row], c = g_cntW[row];
        if (lane >= 16) continue;
        const int2* bk = &g_csrW[p];
        float4 acc = make_float4(0.f, 0.f, 0.f, 0.f);
        for (int k = 0; k < c; k++) {
            int2 e0 = __ldg(&bk[k]);
            float v = __int_as_float(e0.y);
            float4 h = *(const float4*)&g_h2[((size_t)e0.x * BB + b) * D2 + q * 4];
            acc.x = fmaf(v, h.x, acc.x); acc.y = fmaf(v, h.y, acc.y);
            acc.z = fmaf(v, h.z, acc.z); acc.w = fmaf(v, h.w, acc.w);
        }
        *(float4*)&g_T2[((size_t)row * BB + b) * D2 + q * 4] = acc;
    }
}

// ---------------- 10) output heads + tail zeroing ------------------------------------
__global__ void __launch_bounds__(256) k_outz(const float* __restrict__ diag2,
        const float* __restrict__ rw1, const float* __restrict__ rb1,
        const float* __restrict__ rw2, const float* __restrict__ rb2,
        float* __restrict__ out) {
    if (blockIdx.x == 0) {
        int warp = threadIdx.x >> 5;   // 8 warps: b = warp&3, s = warp>>2
        int lane = threadIdx.x & 31;
        int b = warp & 3, s = warp >> 2;
        int n = NN - 2 + s;
        int p = g_ptrWi[n], c = g_cntWi[n];
        float acc = 0.f;
        for (int i = 0; i < c; i++) {
            int2 e = g_csrWi[p + i];
            float coef = __int_as_float(e.y) * __ldg(&diag2[e.x]);
            if (lane < D2) acc = fmaf(coef, g_T2[((size_t)e.x * BB + b) * D2 + lane], acc);
        }
        float v = acc > 0.f ? acc : NEG * acc;
        const float* w = s ? rw2 : rw1;
        float y = (lane < D2) ? v * w[lane] : 0.f;
#pragma unroll
        for (int o = 16; o > 0; o >>= 1) y += __shfl_xor_sync(0xffffffffu, y, o);
        if (lane == 0) out[b * 2 + s] = y + (s ? rb2[0] : rb1[0]);
        __syncthreads();   // everyone done reading cntWi[N-2..N-1]
        if (threadIdx.x < 2)  g_cntWi[NN - 2 + threadIdx.x] = 0;
        if (threadIdx.x == 2) g_nT1 = 0;
        if (threadIdx.x == 3) g_nH2 = 0;
        if (threadIdx.x == 4) g_nT2 = 0;
    } else {
        int i0 = (blockIdx.x - 1) * 256 + threadIdx.x;
        const int stride = 63 * 256;
        for (int i = i0; i < NN - 2; i += stride) g_cntWi[i] = 0;  // last 2 done by block 0
        for (int i = i0; i < RR; i += stride) g_cntW[i] = 0;
        for (int i = i0; i < MW_R; i += stride) { g_mT1[i] = 0u; g_mT2[i] = 0u; }
        for (int i = i0; i < MW_N; i += stride) g_mH2[i] = 0u;
    }
}

// ---------------- launch ----------------
extern "C" void kernel_launch(void* const* d_in, const int* in_sizes, int n_in,
                              void* d_out, int out_size) {
    const int*   wIdx   = (const int*)d_in[0];
    const float* wVal   = (const float*)d_in[1];
    const int*   wiIdx  = (const int*)d_in[2];
    const float* wiVal  = (const float*)d_in[3];
    const float* x      = (const float*)d_in[4];
    const float* W1     = (const float*)d_in[5];
    const float* diag1  = (const float*)d_in[6];
    const float* W2     = (const float*)d_in[7];
    const float* diag2  = (const float*)d_in[8];
    const float* rw1    = (const float*)d_in[9];
    const float* rb1    = (const float*)d_in[10];
    const float* rw2    = (const float*)d_in[11];
    const float* rb2    = (const float*)d_in[12];

    const int* wRows  = wIdx;
    const int* wCols  = wIdx + EE;
    const int* wiRows = wiIdx;
    const int* wiCols = wiIdx + EE;
    float* out = (float*)d_out;

    const int bigGrid = 2 * SCAN_B + H1_HALF;   // 1564 + 12500

    k_hist <<<bigGrid, 256>>>(wiRows, wRows, x, W1);
    k_scanA<<<NB_TOT, 256>>>();
    k_scanB<<<1, 32>>>();
    k_scanC<<<NB_TOT, 256>>>();
    k_scat <<<bigGrid, 256>>>(wiRows, wiCols, wiVal, wRows, wCols, wVal, x, W1);
    k_e1   <<<1, 64>>>();
    k_e2   <<<8, 256>>>();
    k_e3   <<<64, 256>>>();
    k_T1   <<<1024, 256>>>();
    k_x1h2 <<<64, 256>>>(diag1, W2);
    k_T2   <<<8, 256>>>();
    k_outz <<<64, 256>>>(diag2, rw1, rb1, rw2, rb2, out);
}

// round 10
// speedup vs baseline: 1.5534x; 1.5534x over previous
#include <cuda_runtime.h>
#include <cuda_fp16.h>
#include <cstdint>

// Problem constants (fixed by the dataset)
#define BB 4
#define NN 50000
#define RR 100000
#define EE 1600000
#define D1 32
#define D2 16
#define NEG 0.2f

// Bucket capacities (Poisson lambda=16 R-rows / 32 N-rows; overflow prob < 1e-25)
#define CAP_T1 128
#define CAP_X1 192
#define CAP_T2 128
#define CAP_P1 256

#define MW_R ((RR + 31) / 32)
#define MW_N ((NN + 31) / 32)

#define SCAN_T   (EE / 8)                  // 200000 scan threads (8 edges each)
#define SCAN_B   ((SCAN_T + 255) / 256)    // 782 scan blocks
#define H1_W     (NN * BB)                 // 200000 h1 warps (one per (n,b))
#define H1_B     ((H1_W + 7) / 8)          // 25000 h1 blocks (8 warps/block)
#define H1_CHUNK (H1_B / 4)                // 6250 h1 blocks per scan kernel

// Bloom filters (first-level membership pre-check; tiny -> L1-broadcast loads)
#define BLT2_W 64     // 256 B, 2048 bits, bit = r & 2047   (~64 set -> FP 3%)
#define BLH2_W 256    // 1 KB, 8192 bits, bit = n & 8191    (~1K set -> FP 12%)

// ---------------- device scratch (zero-init at module load; left zeroed per call) ----
__device__ __half g_h1[NN * BB * D1];  // 12.8 MB  [n][b][32] fp16
__device__ float g_T1[RR * BB * D1];   // 51.2 MB  [r][b][32]
__device__ float g_h2[NN * BB * D2];   // 12.8 MB  [n][b][16]
__device__ float g_T2[RR * BB * D2];   // 25.6 MB  [r][b][16]

__device__ int  g_cntT1[RR], g_cntX1[NN], g_cntT2[RR], g_cntP1[2];
__device__ int2 g_bT1[RR * CAP_T1];    // (col, val)
__device__ int2 g_bX1[NN * CAP_X1];    // (col, coef)
__device__ int2 g_bT2[RR * CAP_T2];    // (col, val)
__device__ int2 g_bP1[2 * CAP_P1];     // (col, coef)

__device__ unsigned g_mT1[MW_R], g_mT2[MW_R], g_mH2[MW_N];   // exact bit flags
__device__ unsigned g_blT2[BLT2_W], g_blH2[BLH2_W];          // bloom pre-filters

// ---------------- h1 chunk: h1[n][b][:] = x[b][n][:] @ W1, one warp per (n,b) -------
__device__ __forceinline__ void h1_block(int vb, const float* __restrict__ x,
                                         const float* __restrict__ W1) {
    __shared__ float sW[D1 * D1];
    int t = threadIdx.x;
    for (int i = t; i < D1 * D1; i += 256) sW[i] = W1[i];
    __syncthreads();
    int w = vb * 8 + (t >> 5);
    if (w >= H1_W) return;
    int lane = t & 31;
    int n = w >> 2, b = w & 3;
    float xv = x[((size_t)b * NN + n) * D1 + lane];
    float acc = 0.f;
#pragma unroll
    for (int k = 0; k < D1; k++) {
        float xk = __shfl_sync(0xffffffffu, xv, k);
        acc = fmaf(xk, sW[k * D1 + lane], acc);
    }
    g_h1[(size_t)w * D1 + lane] = __float2half(acc);
}

// ---------------- scan kernels: scan blocks first, then an h1 chunk ------------------
// S1: wi-edges into the 2 output nodes -> bP1 + mark mT2 + bloom blT2
__global__ void __launch_bounds__(256) k_s1(const int* __restrict__ wiRows,
        const int* __restrict__ wiCols, const float* __restrict__ wiVals,
        const float* __restrict__ diag2,
        const float* __restrict__ x, const float* __restrict__ W1) {
    if (blockIdx.x >= SCAN_B) { h1_block(blockIdx.x - SCAN_B, x, W1); return; }
    int t = blockIdx.x * 256 + threadIdx.x;
    if (t >= SCAN_T) return;
    int base = t * 8;
    int4 a = __ldg((const int4*)(wiRows + base));
    int4 b4 = __ldg((const int4*)(wiRows + base + 4));
    int r[8] = {a.x, a.y, a.z, a.w, b4.x, b4.y, b4.z, b4.w};
#pragma unroll
    for (int j = 0; j < 8; j++) {
        if (r[j] >= NN - 2) {
            int s = r[j] - (NN - 2);
            int e = base + j;
            int col = __ldg(&wiCols[e]);
            float coef = __ldg(&wiVals[e]) * __ldg(&diag2[col]);
            int slot = atomicAdd(&g_cntP1[s], 1);
            if (slot < CAP_P1) g_bP1[s * CAP_P1 + slot] = make_int2(col, __float_as_int(coef));
            atomicOr(&g_mT2[col >> 5], 1u << (col & 31));
            atomicOr(&g_blT2[(col >> 5) & (BLT2_W - 1)], 1u << (col & 31));
        }
    }
}

// S2: w-edges feeding mT2 rows -> bT2 + mark mH2 + bloom blH2
// Bloom pre-check (2-line array) kills 97% of exact-mask probes.
__global__ void __launch_bounds__(256) k_s2(const int* __restrict__ wRows,
        const int* __restrict__ wCols, const float* __restrict__ wVals,
        const float* __restrict__ x, const float* __restrict__ W1) {
    if (blockIdx.x >= SCAN_B) { h1_block(blockIdx.x - SCAN_B + H1_CHUNK, x, W1); return; }
    int t = blockIdx.x * 256 + threadIdx.x;
    if (t >= SCAN_T) return;
    int base = t * 8;
    int4 a = __ldg((const int4*)(wRows + base));
    int4 b4 = __ldg((const int4*)(wRows + base + 4));
    int r[8] = {a.x, a.y, a.z, a.w, b4.x, b4.y, b4.z, b4.w};
    unsigned bl[8];
#pragma unroll
    for (int j = 0; j < 8; j++) bl[j] = __ldg(&g_blT2[(r[j] >> 5) & (BLT2_W - 1)]);
#pragma unroll
    for (int j = 0; j < 8; j++) {
        if ((bl[j] >> (r[j] & 31)) & 1u) {                       // bloom hit (cheap)
            if ((__ldg(&g_mT2[r[j] >> 5]) >> (r[j] & 31)) & 1u) { // exact check (rare)
                int e = base + j;
                int col = __ldg(&wCols[e]);
                int slot = atomicAdd(&g_cntT2[r[j]], 1);
                if (slot < CAP_T2)
                    g_bT2[r[j] * CAP_T2 + slot] = make_int2(col, __float_as_int(__ldg(&wVals[e])));
                atomicOr(&g_mH2[col >> 5], 1u << (col & 31));
                atomicOr(&g_blH2[(col >> 5) & (BLH2_W - 1)], 1u << (col & 31));
            }
        }
    }
}

// S3: wi-edges feeding mH2 nodes -> bX1 (coef = val*diag1) + mark mT1
// Bloom pre-check (8-line array) kills ~88% of exact-mask probes.
__global__ void __launch_bounds__(256) k_s3(const int* __restrict__ wiRows,
        const int* __restrict__ wiCols, const float* __restrict__ wiVals,
        const float* __restrict__ diag1,
        const float* __restrict__ x, const float* __restrict__ W1) {
    if (blockIdx.x >= SCAN_B) { h1_block(blockIdx.x - SCAN_B + 2 * H1_CHUNK, x, W1); return; }
    int t = blockIdx.x * 256 + threadIdx.x;
    if (t >= SCAN_T) return;
    int base = t * 8;
    int4 a = __ldg((const int4*)(wiRows + base));
    int4 b4 = __ldg((const int4*)(wiRows + base + 4));
    int r[8] = {a.x, a.y, a.z, a.w, b4.x, b4.y, b4.z, b4.w};
    unsigned bl[8];
#pragma unroll
    for (int j = 0; j < 8; j++) bl[j] = __ldg(&g_blH2[(r[j] >> 5) & (BLH2_W - 1)]);
#pragma unroll
    for (int j = 0; j < 8; j++) {
        if ((bl[j] >> (r[j] & 31)) & 1u) {
            if ((__ldg(&g_mH2[r[j] >> 5]) >> (r[j] & 31)) & 1u) {
                int e = base + j;
                int col = __ldg(&wiCols[e]);
                float coef = __ldg(&wiVals[e]) * __ldg(&diag1[col]);
                int slot = atomicAdd(&g_cntX1[r[j]], 1);
                if (slot < CAP_X1)
                    g_bX1[r[j] * CAP_X1 + slot] = make_int2(col, __float_as_int(coef));
                atomicOr(&g_mT1[col >> 5], 1u << (col & 31));
            }
        }
    }
}

// S4: w-edges feeding mT1 rows -> bT1 (28% hit: stream cols+vals; no bloom useful)
__global__ void __launch_bounds__(256) k_s4(const int* __restrict__ wRows,
        const int* __restrict__ wCols, const float* __restrict__ wVals,
        const float* __restrict__ x, const float* __restrict__ W1) {
    if (blockIdx.x >= SCAN_B) { h1_block(blockIdx.x - SCAN_B + 3 * H1_CHUNK, x, W1); return; }
    int t = blockIdx.x * 256 + threadIdx.x;
    if (t >= SCAN_T) return;
    int base = t * 8;
    int4 a = __ldg((const int4*)(wRows + base));
    int4 b4 = __ldg((const int4*)(wRows + base + 4));
    int4 c0 = __ldg((const int4*)(wCols + base));
    int4 c1 = __ldg((const int4*)(wCols + base + 4));
    float4 v0 = __ldg((const float4*)(wVals + base));
    float4 v1 = __ldg((const float4*)(wVals + base + 4));
    int r[8] = {a.x, a.y, a.z, a.w, b4.x, b4.y, b4.z, b4.w};
    int cc[8] = {c0.x, c0.y, c0.z, c0.w, c1.x, c1.y, c1.z, c1.w};
    float vv[8] = {v0.x, v0.y, v0.z, v0.w, v1.x, v1.y, v1.z, v1.w};
    unsigned m[8];
#pragma unroll
    for (int j = 0; j < 8; j++) m[j] = __ldg(&g_mT1[r[j] >> 5]);
#pragma unroll
    for (int j = 0; j < 8; j++) {
        if ((m[j] >> (r[j] & 31)) & 1u) {
            int slot = atomicAdd(&g_cntT1[r[j]], 1);
            if (slot < CAP_T1)
                g_bT1[r[j] * CAP_T1 + slot] = make_int2(cc[j], __float_as_int(vv[j]));
        }
    }
}

// ---------------- T1[row] = sum_e v_e * h1[col_e]; one warp per row, full width ------
__global__ void __launch_bounds__(256) k_T1() {
    int w = (blockIdx.x * 256 + threadIdx.x) >> 5;
    if (w >= RR) return;
    int c = g_cntT1[w];
    if (c == 0) return;
    if (c > CAP_T1) c = CAP_T1;
    int lane = threadIdx.x & 31;
    int b = lane >> 3, q = lane & 7;
    const int2* bk = &g_bT1[w * CAP_T1];
    float4 acc = make_float4(0.f, 0.f, 0.f, 0.f);
    int k = 0;
    for (; k + 4 <= c; k += 4) {
        int2 e0 = __ldg(&bk[k]),     e1 = __ldg(&bk[k + 1]);
        int2 e2 = __ldg(&bk[k + 2]), e3 = __ldg(&bk[k + 3]);
        uint2 u0 = *(const uint2*)&g_h1[((size_t)e0.x * BB + b) * D1 + q * 4];
        uint2 u1 = *(const uint2*)&g_h1[((size_t)e1.x * BB + b) * D1 + q * 4];
        uint2 u2 = *(const uint2*)&g_h1[((size_t)e2.x * BB + b) * D1 + q * 4];
        uint2 u3 = *(const uint2*)&g_h1[((size_t)e3.x * BB + b) * D1 + q * 4];
        float v0 = __int_as_float(e0.y), v1 = __int_as_float(e1.y);
        float v2 = __int_as_float(e2.y), v3 = __int_as_float(e3.y);
        float2 a01, a23;
        a01 = __half22float2(*(__half2*)&u0.x); a23 = __half22float2(*(__half2*)&u0.y);
        acc.x = fmaf(v0, a01.x, acc.x); acc.y = fmaf(v0, a01.y, acc.y);
        acc.z = fmaf(v0, a23.x, acc.z); acc.w = fmaf(v0, a23.y, acc.w);
        a01 = __half22float2(*(__half2*)&u1.x); a23 = __half22float2(*(__half2*)&u1.y);
        acc.x = fmaf(v1, a01.x, acc.x); acc.y = fmaf(v1, a01.y, acc.y);
        acc.z = fmaf(v1, a23.x, acc.z); acc.w = fmaf(v1, a23.y, acc.w);
        a01 = __half22float2(*(__half2*)&u2.x); a23 = __half22float2(*(__half2*)&u2.y);
        acc.x = fmaf(v2, a01.x, acc.x); acc.y = fmaf(v2, a01.y, acc.y);
        acc.z = fmaf(v2, a23.x, acc.z); acc.w = fmaf(v2, a23.y, acc.w);
        a01 = __half22float2(*(__half2*)&u3.x); a23 = __half22float2(*(__half2*)&u3.y);
        acc.x = fmaf(v3, a01.x, acc.x); acc.y = fmaf(v3, a01.y, acc.y);
        acc.z = fmaf(v3, a23.x, acc.z); acc.w = fmaf(v3, a23.y, acc.w);
    }
    for (; k < c; k++) {
        int2 e0 = __ldg(&bk[k]);
        float v = __int_as_float(e0.y);
        uint2 u0 = *(const uint2*)&g_h1[((size_t)e0.x * BB + b) * D1 + q * 4];
        float2 a01 = __half22float2(*(__half2*)&u0.x);
        float2 a23 = __half22float2(*(__half2*)&u0.y);
        acc.x = fmaf(v, a01.x, acc.x); acc.y = fmaf(v, a01.y, acc.y);
        acc.z = fmaf(v, a23.x, acc.z); acc.w = fmaf(v, a23.y, acc.w);
    }
    *(float4*)&g_T1[((size_t)w * BB + b) * D1 + q * 4] = acc;
}

// ---------------- fused x1 + h2, one warp per node, full width -----------------------
__global__ void __launch_bounds__(256) k_x1h2(const float* __restrict__ W2) {
    __shared__ float sW[D1 * D2];
    __shared__ float sX[8][BB * D1];
    int t = threadIdx.x;
    for (int i = t; i < D1 * D2; i += 256) sW[i] = W2[i];
    __syncthreads();
    int node = (blockIdx.x * 256 + t) >> 5;
    if (node >= NN) return;
    int c = g_cntX1[node];
    if (c == 0) return;
    if (c > CAP_X1) c = CAP_X1;
    int lane = t & 31;
    int wlocal = t >> 5;
    int b = lane >> 3, q = lane & 7;
    const int2* bk = &g_bX1[node * CAP_X1];
    float4 acc = make_float4(0.f, 0.f, 0.f, 0.f);
    int k = 0;
    for (; k + 2 <= c; k += 2) {
        int2 e0 = __ldg(&bk[k]), e1 = __ldg(&bk[k + 1]);
        float4 t0 = *(const float4*)&g_T1[((size_t)e0.x * BB + b) * D1 + q * 4];
        float4 t1 = *(const float4*)&g_T1[((size_t)e1.x * BB + b) * D1 + q * 4];
        float v0 = __int_as_float(e0.y), v1 = __int_as_float(e1.y);
        acc.x = fmaf(v0, t0.x, acc.x); acc.y = fmaf(v0, t0.y, acc.y);
        acc.z = fmaf(v0, t0.z, acc.z); acc.w = fmaf(v0, t0.w, acc.w);
        acc.x = fmaf(v1, t1.x, acc.x); acc.y = fmaf(v1, t1.y, acc.y);
        acc.z = fmaf(v1, t1.z, acc.z); acc.w = fmaf(v1, t1.w, acc.w);
    }
    for (; k < c; k++) {
        int2 e0 = __ldg(&bk[k]);
        float v = __int_as_float(e0.y);
        float4 tv = *(const float4*)&g_T1[((size_t)e0.x * BB + b) * D1 + q * 4];
        acc.x = fmaf(v, tv.x, acc.x); acc.y = fmaf(v, tv.y, acc.y);
        acc.z = fmaf(v, tv.z, acc.z); acc.w = fmaf(v, tv.w, acc.w);
    }
    acc.x = acc.x > 0.f ? acc.x : NEG * acc.x;
    acc.y = acc.y > 0.f ? acc.y : NEG * acc.y;
    acc.z = acc.z > 0.f ? acc.z : NEG * acc.z;
    acc.w = acc.w > 0.f ? acc.w : NEG * acc.w;
    *(float4*)&sX[wlocal][b * D1 + q * 4] = acc;
    __syncwarp();
    int j = lane & 7;
    const float* xr = &sX[wlocal][b * D1];
    float a0 = 0.f, a1 = 0.f;
#pragma unroll
    for (int kk = 0; kk < D1; kk++) {
        float xv = xr[kk];
        a0 = fmaf(xv, sW[kk * D2 + j], a0);
        a1 = fmaf(xv, sW[kk * D2 + j + 8], a1);
    }
    g_h2[((size_t)node * BB + b) * D2 + j] = a0;
    g_h2[((size_t)node * BB + b) * D2 + j + 8] = a1;
}

// ---------------- T2[row] = sum_e v_e * h2[col_e]; one warp per row, full width ------
__global__ void __launch_bounds__(256) k_T2() {
    int w = (blockIdx.x * 256 + threadIdx.x) >> 5;
    if (w >= RR) return;
    int c = g_cntT2[w];
    if (c == 0) return;
    if (c > CAP_T2) c = CAP_T2;
    int lane = threadIdx.x & 31;
    if (lane >= 16) return;
    int b = lane >> 2, q = lane & 3;
    const int2* bk = &g_bT2[w * CAP_T2];
    float4 acc = make_float4(0.f, 0.f, 0.f, 0.f);
    for (int k = 0; k < c; k++) {
        int2 e0 = __ldg(&bk[k]);
        float v = __int_as_float(e0.y);
        float4 h = *(const float4*)&g_h2[((size_t)e0.x * BB + b) * D2 + q * 4];
        acc.x = fmaf(v, h.x, acc.x); acc.y = fmaf(v, h.y, acc.y);
        acc.z = fmaf(v, h.z, acc.z); acc.w = fmaf(v, h.w, acc.w);
    }
    *(float4*)&g_T2[((size_t)w * BB + b) * D2 + q * 4] = acc;
}

// ---------------- final heads + tail zeroing (state left clean for next call) --------
__global__ void __launch_bounds__(256) k_outz(const float* __restrict__ rw1,
        const float* __restrict__ rb1, const float* __restrict__ rw2,
        const float* __restrict__ rb2, float* __restrict__ out) {
    if (blockIdx.x == 0) {
        int warp = threadIdx.x >> 5;   // 8 warps: b = warp&3, s = warp>>2
        int lane = threadIdx.x & 31;
        int b = warp & 3, s = warp >> 2;
        int c = g_cntP1[s]; if (c > CAP_P1) c = CAP_P1;
        float acc = 0.f;
        for (int i = 0; i < c; i++) {
            int2 e = g_bP1[s * CAP_P1 + i];
            float coef = __int_as_float(e.y);
            if (lane < D2) acc = fmaf(coef, g_T2[((size_t)e.x * BB + b) * D2 + lane], acc);
        }
        float v = acc > 0.f ? acc : NEG * acc;
        const float* w = s ? rw2 : rw1;
        float y = (lane < D2) ? v * w[lane] : 0.f;
#pragma unroll
        for (int o = 16; o > 0; o >>= 1) y += __shfl_xor_sync(0xffffffffu, y, o);
        if (lane == 0) out[b * 2 + s] = y + (s ? rb2[0] : rb1[0]);
        __syncthreads();                       // all warps done reading g_cntP1
        if (threadIdx.x < 2) g_cntP1[threadIdx.x] = 0;
        if (threadIdx.x >= 32 && threadIdx.x < 32 + BLT2_W) g_blT2[threadIdx.x - 32] = 0u;
    } else {
        int i0 = (blockIdx.x - 1) * 256 + threadIdx.x;
        const int stride = 64 * 256;
        for (int i = i0; i < RR; i += stride) { g_cntT1[i] = 0; g_cntT2[i] = 0; }
        for (int i = i0; i < NN; i += stride) g_cntX1[i] = 0;
        for (int i = i0; i < MW_R; i += stride) { g_mT1[i] = 0u; g_mT2[i] = 0u; }
        for (int i = i0; i < MW_N; i += stride) g_mH2[i] = 0u;
        for (int i = i0; i < BLH2_W; i += stride) g_blH2[i] = 0u;
    }
}

// ---------------- launch ----------------
extern "C" void kernel_launch(void* const* d_in, const int* in_sizes, int n_in,
                              void* d_out, int out_size) {
    const int*   wIdx   = (const int*)d_in[0];
    const float* wVal   = (const float*)d_in[1];
    const int*   wiIdx  = (const int*)d_in[2];
    const float* wiVal  = (const float*)d_in[3];
    const float* x      = (const float*)d_in[4];
    const float* W1     = (const float*)d_in[5];
    const float* diag1  = (const float*)d_in[6];
    const float* W2     = (const float*)d_in[7];
    const float* diag2  = (const float*)d_in[8];
    const float* rw1    = (const float*)d_in[9];
    const float* rb1    = (const float*)d_in[10];
    const float* rw2    = (const float*)d_in[11];
    const float* rb2    = (const float*)d_in[12];

    const int* wRows  = wIdx;
    const int* wCols  = wIdx + EE;
    const int* wiRows = wiIdx;
    const int* wiCols = wiIdx + EE;
    float* out = (float*)d_out;

    const int mixGrid = SCAN_B + H1_CHUNK;   // 782 + 6250 (R4 layout)

    k_s1<<<mixGrid, 256>>>(wiRows, wiCols, wiVal, diag2, x, W1);
    k_s2<<<mixGrid, 256>>>(wRows, wCols, wVal, x, W1);
    k_s3<<<mixGrid, 256>>>(wiRows, wiCols, wiVal, diag1, x, W1);
    k_s4<<<mixGrid, 256>>>(wRows, wCols, wVal, x, W1);
    k_T1<<<(RR * 32 + 255) / 256, 256>>>();
    k_x1h2<<<(NN * 32 + 255) / 256, 256>>>(W2);
    k_T2<<<(RR * 32 + 255) / 256, 256>>>();
    k_outz<<<65, 256>>>(rw1, rb1, rw2, rb2, out);
}